// round 8
// baseline (speedup 1.0000x reference)
#include <cuda_runtime.h>

#define N_HALF 4096
#define TWO_N  8192
#define D      8
#define NT     16                    // row/col tiles of 512
#define RT     512
#define BT     256                   // threads per block
#define ROWS_PT 2                    // rows per thread (RT = 2*BT)
#define CSPLIT 8                     // column octants per tile
#define CT     64                    // columns per block
#define NSLOT  (NT * CSPLIT)         // 128 partial slots per row
#define NPAIR  (NT * (NT + 1) / 2)   // 136 tile pairs
#define NBLK   (NPAIR * CSPLIT)      // 1088 blocks

#define LN2_F          0.6931471805599453f
#define HALF_LN2SQ_F   0.24022650695910072f   // ln2^2 / 2
#define HALF_LN2_F     0.34657359027997264f   // ln2 / 2
#define BOUNDARY_F     0.99999f

// __device__ scratch (allocation-free rule)
__device__ float        g_denom[NSLOT * TWO_N];   // 4 MB partials
__device__ float        g_partial[256];
__device__ unsigned int g_cnt;                     // zero-init at load

typedef unsigned long long u64;

__device__ __forceinline__ float fast_sqrt(float x) { float y; asm("sqrt.approx.f32 %0, %1;" : "=f"(y) : "f"(x)); return y; }
__device__ __forceinline__ float fast_lg2(float x)  { float y; asm("lg2.approx.f32 %0, %1;"  : "=f"(y) : "f"(x)); return y; }
__device__ __forceinline__ float fast_rcp(float x)  { float y; asm("rcp.approx.f32 %0, %1;"  : "=f"(y) : "f"(x)); return y; }
__device__ __forceinline__ float fast_ex2(float x)  { float y; asm("ex2.approx.f32 %0, %1;"  : "=f"(y) : "f"(x)); return y; }

__device__ __forceinline__ u64 pack2(float lo, float hi) {
    u64 r; asm("mov.b64 %0, {%1,%2};" : "=l"(r) : "f"(lo), "f"(hi)); return r;
}
__device__ __forceinline__ void unpack2(u64 v, float& lo, float& hi) {
    asm("mov.b64 {%0,%1}, %2;" : "=f"(lo), "=f"(hi) : "l"(v));
}
__device__ __forceinline__ u64 fma2(u64 a, u64 b, u64 c) {
    u64 r; asm("fma.rn.f32x2 %0, %1, %2, %3;" : "=l"(r) : "l"(a), "l"(b), "l"(c)); return r;
}

// ---- shared building blocks (identical in both kernels: bit-exact self-term)
__device__ __forceinline__ void load_point(const float* __restrict__ zi,
                                           const float* __restrict__ zj,
                                           int i, float4& a, float4& b) {
    const float* src = (i < N_HALF) ? (zi + (size_t)i * D)
                                    : (zj + (size_t)(i - N_HALF) * D);
    a = *reinterpret_cast<const float4*>(src);
    b = *reinterpret_cast<const float4*>(src + 4);
}

__device__ __forceinline__ float raw8(const float4& a, const float4& b) {
    float d = __fmul_rn(a.x, a.x);
    d = fmaf(a.y, a.y, d); d = fmaf(a.z, a.z, d); d = fmaf(a.w, a.w, d);
    d = fmaf(b.x, b.x, d); d = fmaf(b.y, b.y, d); d = fmaf(b.z, b.z, d);
    d = fmaf(b.w, b.w, d);
    return d;
}

// row-side augmented vector: a = [-4*inv*z(8); 2*inv*raw; 2*inv]
__device__ __forceinline__ void build_a(const float4& a, const float4& b, u64 A[5]) {
    float raw = raw8(a, b);
    float inv = 1.0f / (1.0f - fminf(raw, BOUNDARY_F));
    float m   = __fmul_rn(-4.0f, inv);
    A[0] = pack2(__fmul_rn(m, a.x), __fmul_rn(m, a.y));
    A[1] = pack2(__fmul_rn(m, a.z), __fmul_rn(m, a.w));
    A[2] = pack2(__fmul_rn(m, b.x), __fmul_rn(m, b.y));
    A[3] = pack2(__fmul_rn(m, b.z), __fmul_rn(m, b.w));
    float i2 = __fadd_rn(inv, inv);
    A[4] = pack2(__fmul_rn(i2, raw), i2);
}

// col-side augmented vector: b = [inv*z(8); inv; inv*raw]
__device__ __forceinline__ void build_b(const float4& a, const float4& b, u64 B[5]) {
    float raw = raw8(a, b);
    float inv = 1.0f / (1.0f - fminf(raw, BOUNDARY_F));
    B[0] = pack2(__fmul_rn(inv, a.x), __fmul_rn(inv, a.y));
    B[1] = pack2(__fmul_rn(inv, a.z), __fmul_rn(inv, a.w));
    B[2] = pack2(__fmul_rn(inv, b.x), __fmul_rn(inv, b.y));
    B[3] = pack2(__fmul_rn(inv, b.z), __fmul_rn(inv, b.w));
    B[4] = pack2(inv, __fmul_rn(inv, raw));
}

// x = max(1 + a.b, 1)
__device__ __forceinline__ float dotx(const u64 A[5], const u64 B[5], u64 c10) {
    u64 s = fma2(A[4], B[4], c10);
    s = fma2(A[0], B[0], s);
    s = fma2(A[1], B[1], s);
    s = fma2(A[2], B[2], s);
    s = fma2(A[3], B[3], s);
    float lo, hi;
    unpack2(s, lo, hi);
    return fmaxf(__fadd_rn(lo, hi), 1.0f);
}

// e = exp(2*sim) = ex2( 1 / ((1 + arcosh(x)) * ln2/2) )
__device__ __forceinline__ float chain_e(float x) {
    float x2 = fmaf(x, x, -1.0f);                  // >= 0 since x >= 1
    float s  = fast_sqrt(x2);                      // MUFU
    float l  = fast_lg2(__fadd_rn(x, s));          // MUFU
    float dn = fmaf(l, HALF_LN2SQ_F, HALF_LN2_F);  // (1+dist)*ln2/2
    return fast_ex2(fast_rcp(dn));                 // MUFU, MUFU
}
// sim = 1/(1+arcosh(x))  (finalize positives only; 2N evals)
__device__ __forceinline__ float chain_sim(float x) {
    float x2 = fmaf(x, x, -1.0f);
    float s  = fast_sqrt(x2);
    float l  = fast_lg2(__fadd_rn(x, s));
    return fast_rcp(fmaf(l, LN2_F, 1.0f));
}

// ---------------------------------------------------------------------------
// Kernel 1: symmetric pairwise tiles -> partial softmax denominators
// grid = 1088, block = 256 (2 rows/thread, 64 columns/block)
// ---------------------------------------------------------------------------
__global__ void __launch_bounds__(BT)
pair_kernel(const float* __restrict__ zi, const float* __restrict__ zj) {
    __shared__ u64   sb[5][CT];     // column augmented vectors (SoA)
    __shared__ float wacc[8][CT];   // per-warp column sums

    const int t    = threadIdx.x;
    const int lane = t & 31;
    const int w    = t >> 5;
    const int nxt  = (lane + 1) & 31;

    // decode (a, b, h)
    int p = blockIdx.x >> 3;
    int h = blockIdx.x & 7;
    int a = 0, rem = p;
    while (rem >= NT - a) { rem -= NT - a; ++a; }
    int b = a + rem;
    const bool diag = (a == b);
    const int jbase = b * RT + h * CT;

    // stage 64 columns
    if (t < CT) {
        float4 ca, cb;
        load_point(zi, zj, jbase + t, ca, cb);
        u64 B[5];
        build_b(ca, cb, B);
        sb[0][t] = B[0]; sb[1][t] = B[1]; sb[2][t] = B[2];
        sb[3][t] = B[3]; sb[4][t] = B[4];
    }

    // build 2 row vectors
    u64 A[ROWS_PT][5];
    #pragma unroll
    for (int r = 0; r < ROWS_PT; ++r) {
        float4 ra, rb;
        load_point(zi, zj, a * RT + r * BT + t, ra, rb);
        build_a(ra, rb, A[r]);
    }

    const u64 c10 = pack2(1.0f, 0.0f);

    __syncthreads();

    float racc0 = 0.0f, racc1 = 0.0f;

    if (diag) {
        #pragma unroll 4
        for (int c = 0; c < CT; ++c) {                    // broadcast LDS
            u64 B[5] = { sb[0][c], sb[1][c], sb[2][c], sb[3][c], sb[4][c] };
            racc0 += chain_e(dotx(A[0], B, c10));
            racc1 += chain_e(dotx(A[1], B, c10));
        }
    } else {
        #pragma unroll
        for (int g = 0; g < CT / 32; ++g) {
            float cacc = 0.0f;                            // systolic ring acc
            #pragma unroll 4
            for (int k = 0; k < 32; ++k) {
                int c = (g << 5) + ((lane + k) & 31);     // conflict-free
                u64 B[5] = { sb[0][c], sb[1][c], sb[2][c], sb[3][c], sb[4][c] };
                float e0 = chain_e(dotx(A[0], B, c10));
                float e1 = chain_e(dotx(A[1], B, c10));
                racc0 += e0;
                racc1 += e1;
                cacc += (e0 + e1);
                cacc = __shfl_sync(0xFFFFFFFFu, cacc, nxt, 32);
            }
            wacc[w][(g << 5) + lane] = cacc;              // lane holds col 'lane'
        }
    }

    // row-side partials: slot (b, h)
    const size_t rbase = (size_t)(b * CSPLIT + h) * TWO_N + a * RT + t;
    g_denom[rbase]              = racc0;
    g_denom[rbase + (size_t)BT] = racc1;

    // column-side partials: slot (a, h)
    if (!diag) {
        __syncthreads();
        if (t < CT) {
            float c = ((wacc[0][t] + wacc[1][t]) + (wacc[2][t] + wacc[3][t]))
                    + ((wacc[4][t] + wacc[5][t]) + (wacc[6][t] + wacc[7][t]));
            g_denom[(size_t)(a * CSPLIT + h) * TWO_N + jbase + t] = c;
        }
    }
}

// ---------------------------------------------------------------------------
// Kernel 2: denom combine (8 threads/row x 16 slots) + positives + full reduce
// grid = 256, block = 256 (32 rows per block); last block finalizes
// ---------------------------------------------------------------------------
__global__ void __launch_bounds__(256)
fin_kernel(const float* __restrict__ zi, const float* __restrict__ zj,
           float* __restrict__ out) {
    __shared__ float sacc[8][32];
    const int t = threadIdx.x;
    const int r = t & 31;          // row within block
    const int g = t >> 5;          // slot group (16 slots each)
    const int i = blockIdx.x * 32 + r;

    float d = 0.0f;
    #pragma unroll
    for (int c = 0; c < 16; ++c)
        d += g_denom[(size_t)(g * 16 + c) * TWO_N + i];
    sacc[g][r] = d;
    __syncthreads();

    if (g == 0) {                  // warp 0 finishes the 32 rows
        float denom = 0.0f;
        #pragma unroll
        for (int ww = 0; ww < 8; ++ww) denom += sacc[ww][r];

        const u64 c10 = pack2(1.0f, 0.0f);

        float4 ua, ub;
        load_point(zi, zj, i, ua, ub);
        u64 Ai[5], Bi[5];
        build_a(ua, ub, Ai);
        build_b(ua, ub, Bi);
        denom -= chain_e(dotx(Ai, Bi, c10));      // bit-exact self cancel

        const int pp = (i < N_HALF) ? (i + N_HALF) : (i - N_HALF);
        float4 va, vb;
        load_point(zi, zj, pp, va, vb);
        u64 Bp[5];
        build_b(va, vb, Bp);
        float sim = chain_sim(dotx(Ai, Bp, c10));

        float loss = fast_lg2(denom) * LN2_F - 2.0f * sim;
        #pragma unroll
        for (int s = 16; s > 0; s >>= 1)
            loss += __shfl_xor_sync(0xFFFFFFFFu, loss, s);

        unsigned tk = 0u;
        if (r == 0) {
            g_partial[blockIdx.x] = loss;
            __threadfence();
            tk = atomicAdd(&g_cnt, 1u) + 1u;
        }
        tk = __shfl_sync(0xFFFFFFFFu, tk, 0);
        if (tk == 256u) {                          // last block finalizes
            __threadfence();
            float v = 0.0f;
            #pragma unroll
            for (int j = 0; j < 8; ++j) v += g_partial[r + j * 32];
            #pragma unroll
            for (int s = 16; s > 0; s >>= 1)
                v += __shfl_xor_sync(0xFFFFFFFFu, v, s);
            if (r == 0) {
                out[0] = v / (float)TWO_N;
                g_cnt = 0;                         // reset for next replay
            }
        }
    }
}

// ---------------------------------------------------------------------------
extern "C" void kernel_launch(void* const* d_in, const int* in_sizes, int n_in,
                              void* d_out, int out_size) {
    const float* zi = (const float*)d_in[0];
    const float* zj = (const float*)d_in[1];
    float* out = (float*)d_out;

    pair_kernel<<<NBLK, BT>>>(zi, zj);
    fin_kernel<<<256, 256>>>(zi, zj, out);
}

// round 9
// speedup vs baseline: 1.0446x; 1.0446x over previous
#include <cuda_runtime.h>

#define N_HALF 4096
#define TWO_N  8192
#define D      8
#define NT     16                    // row/col tiles of 512
#define RT     512
#define BT     128                   // threads per block
#define ROWS_PT 4                    // rows per thread (RT = 4*BT)
#define CSPLIT 8                     // column octants per tile
#define CT     64                    // columns per block
#define NSLOT  (NT * CSPLIT)         // 128 partial slots per row
#define NPAIR  (NT * (NT + 1) / 2)   // 136 tile pairs
#define NITEM  (NPAIR * CSPLIT)      // 1088 work items
#define GRID   544                   // blocks: 2 equal items per block, 1 wave

#define LN2_F          0.6931471805599453f
#define HALF_LN2SQ_F   0.24022650695910072f   // ln2^2 / 2
#define HALF_LN2_F     0.34657359027997264f   // ln2 / 2
#define BOUNDARY_F     0.99999f

// __device__ scratch (allocation-free rule)
__device__ float        g_denom[NSLOT * TWO_N];   // 4 MB partials
__device__ float        g_partial[256];
__device__ unsigned int g_cnt;                     // zero-init at load

typedef unsigned long long u64;

__device__ __forceinline__ float fast_sqrt(float x) { float y; asm("sqrt.approx.f32 %0, %1;" : "=f"(y) : "f"(x)); return y; }
__device__ __forceinline__ float fast_lg2(float x)  { float y; asm("lg2.approx.f32 %0, %1;"  : "=f"(y) : "f"(x)); return y; }
__device__ __forceinline__ float fast_ex2(float x)  { float y; asm("ex2.approx.f32 %0, %1;"  : "=f"(y) : "f"(x)); return y; }

// Reciprocal on the FMA/ALU pipes (keeps MUFU free): seed + 2 Newton steps.
__device__ __forceinline__ float rcp_alu(float d) {
    float y = __int_as_float(0x7EF311C3 - __float_as_int(d));
    y = __fmul_rn(y, fmaf(-d, y, 2.0f));
    y = __fmul_rn(y, fmaf(-d, y, 2.0f));
    return y;
}

__device__ __forceinline__ u64 pack2(float lo, float hi) {
    u64 r; asm("mov.b64 %0, {%1,%2};" : "=l"(r) : "f"(lo), "f"(hi)); return r;
}
__device__ __forceinline__ void unpack2(u64 v, float& lo, float& hi) {
    asm("mov.b64 {%0,%1}, %2;" : "=f"(lo), "=f"(hi) : "l"(v));
}
__device__ __forceinline__ u64 fma2(u64 a, u64 b, u64 c) {
    u64 r; asm("fma.rn.f32x2 %0, %1, %2, %3;" : "=l"(r) : "l"(a), "l"(b), "l"(c)); return r;
}

// ---- shared building blocks (identical in both kernels: bit-exact self-term)
__device__ __forceinline__ void load_point(const float* __restrict__ zi,
                                           const float* __restrict__ zj,
                                           int i, float4& a, float4& b) {
    const float* src = (i < N_HALF) ? (zi + (size_t)i * D)
                                    : (zj + (size_t)(i - N_HALF) * D);
    a = *reinterpret_cast<const float4*>(src);
    b = *reinterpret_cast<const float4*>(src + 4);
}

__device__ __forceinline__ float raw8(const float4& a, const float4& b) {
    float d = __fmul_rn(a.x, a.x);
    d = fmaf(a.y, a.y, d); d = fmaf(a.z, a.z, d); d = fmaf(a.w, a.w, d);
    d = fmaf(b.x, b.x, d); d = fmaf(b.y, b.y, d); d = fmaf(b.z, b.z, d);
    d = fmaf(b.w, b.w, d);
    return d;
}

// row-side augmented vector: a = [-4*inv*z(8); 2*inv*raw; 2*inv]
__device__ __forceinline__ void build_a(const float4& a, const float4& b, u64 A[5]) {
    float raw = raw8(a, b);
    float inv = 1.0f / (1.0f - fminf(raw, BOUNDARY_F));
    float m   = __fmul_rn(-4.0f, inv);
    A[0] = pack2(__fmul_rn(m, a.x), __fmul_rn(m, a.y));
    A[1] = pack2(__fmul_rn(m, a.z), __fmul_rn(m, a.w));
    A[2] = pack2(__fmul_rn(m, b.x), __fmul_rn(m, b.y));
    A[3] = pack2(__fmul_rn(m, b.z), __fmul_rn(m, b.w));
    float i2 = __fadd_rn(inv, inv);
    A[4] = pack2(__fmul_rn(i2, raw), i2);
}

// col-side augmented vector: b = [inv*z(8); inv; inv*raw]
__device__ __forceinline__ void build_b(const float4& a, const float4& b, u64 B[5]) {
    float raw = raw8(a, b);
    float inv = 1.0f / (1.0f - fminf(raw, BOUNDARY_F));
    B[0] = pack2(__fmul_rn(inv, a.x), __fmul_rn(inv, a.y));
    B[1] = pack2(__fmul_rn(inv, a.z), __fmul_rn(inv, a.w));
    B[2] = pack2(__fmul_rn(inv, b.x), __fmul_rn(inv, b.y));
    B[3] = pack2(__fmul_rn(inv, b.z), __fmul_rn(inv, b.w));
    B[4] = pack2(inv, __fmul_rn(inv, raw));
}

// x = max(1 + a.b, 1)
__device__ __forceinline__ float dotx(const u64 A[5], const u64 B[5], u64 c10) {
    u64 s = fma2(A[4], B[4], c10);
    s = fma2(A[0], B[0], s);
    s = fma2(A[1], B[1], s);
    s = fma2(A[2], B[2], s);
    s = fma2(A[3], B[3], s);
    float lo, hi;
    unpack2(s, lo, hi);
    return fmaxf(__fadd_rn(lo, hi), 1.0f);
}

// e = exp(2*sim) = ex2( 1 / ((1 + arcosh(x)) * ln2/2) )   -- 3 MUFU + ALU rcp
__device__ __forceinline__ float chain_e(float x) {
    float x2 = fmaf(x, x, -1.0f);                  // >= 0 since x >= 1
    float s  = fast_sqrt(x2);                      // MUFU
    float l  = fast_lg2(__fadd_rn(x, s));          // MUFU
    float dn = fmaf(l, HALF_LN2SQ_F, HALF_LN2_F);  // (1+dist)*ln2/2
    return fast_ex2(rcp_alu(dn));                  // MUFU
}
// sim = 1/(1+arcosh(x))  (finalize positives only; 2N evals)
__device__ __forceinline__ float chain_sim(float x) {
    float x2 = fmaf(x, x, -1.0f);
    float s  = fast_sqrt(x2);
    float l  = fast_lg2(__fadd_rn(x, s));
    return rcp_alu(fmaf(l, LN2_F, 1.0f));
}

// ---------------------------------------------------------------------------
// Kernel 1: symmetric pairwise tiles -> partial softmax denominators
// grid = 544 blocks x 128 threads; each block runs 2 equal work items
// ---------------------------------------------------------------------------
__global__ void __launch_bounds__(BT)
pair_kernel(const float* __restrict__ zi, const float* __restrict__ zj) {
    __shared__ u64   sb[5][CT];     // column augmented vectors (SoA)
    __shared__ float wacc[4][CT];   // per-warp column sums

    const int t    = threadIdx.x;
    const int lane = t & 31;
    const int w    = t >> 5;
    const int nxt  = (lane + 1) & 31;
    const u64 c10  = pack2(1.0f, 0.0f);

    #pragma unroll 1
    for (int item = blockIdx.x; item < NITEM; item += GRID) {
        // decode (a, b, h)
        int p = item >> 3;
        int h = item & 7;
        int a = 0, rem = p;
        while (rem >= NT - a) { rem -= NT - a; ++a; }
        int b = a + rem;
        const bool diag = (a == b);
        const int jbase = b * RT + h * CT;

        __syncthreads();   // protect sb/wacc from previous item's readers

        // stage 64 columns
        if (t < CT) {
            float4 ca, cb;
            load_point(zi, zj, jbase + t, ca, cb);
            u64 B[5];
            build_b(ca, cb, B);
            sb[0][t] = B[0]; sb[1][t] = B[1]; sb[2][t] = B[2];
            sb[3][t] = B[3]; sb[4][t] = B[4];
        }

        // build 4 row vectors
        u64 A[ROWS_PT][5];
        #pragma unroll
        for (int r = 0; r < ROWS_PT; ++r) {
            float4 ra, rb;
            load_point(zi, zj, a * RT + r * BT + t, ra, rb);
            build_a(ra, rb, A[r]);
        }

        __syncthreads();

        float racc[ROWS_PT] = {0.f, 0.f, 0.f, 0.f};

        if (diag) {
            #pragma unroll 4
            for (int c = 0; c < CT; ++c) {                    // broadcast LDS
                u64 B[5] = { sb[0][c], sb[1][c], sb[2][c], sb[3][c], sb[4][c] };
                #pragma unroll
                for (int r = 0; r < ROWS_PT; ++r)
                    racc[r] += chain_e(dotx(A[r], B, c10));
            }
        } else {
            #pragma unroll
            for (int g = 0; g < CT / 32; ++g) {
                float cacc = 0.0f;                            // systolic ring acc
                #pragma unroll 4
                for (int k = 0; k < 32; ++k) {
                    int c = (g << 5) + ((lane + k) & 31);     // conflict-free
                    u64 B[5] = { sb[0][c], sb[1][c], sb[2][c], sb[3][c], sb[4][c] };
                    float e0 = chain_e(dotx(A[0], B, c10));
                    float e1 = chain_e(dotx(A[1], B, c10));
                    float e2 = chain_e(dotx(A[2], B, c10));
                    float e3 = chain_e(dotx(A[3], B, c10));
                    racc[0] += e0; racc[1] += e1; racc[2] += e2; racc[3] += e3;
                    cacc += ((e0 + e1) + (e2 + e3));
                    cacc = __shfl_sync(0xFFFFFFFFu, cacc, nxt, 32);
                }
                wacc[w][(g << 5) + lane] = cacc;              // lane holds col 'lane'
            }
        }

        // row-side partials: slot (b, h)
        const size_t rbase = (size_t)(b * CSPLIT + h) * TWO_N + a * RT + t;
        #pragma unroll
        for (int r = 0; r < ROWS_PT; ++r)
            g_denom[rbase + (size_t)r * BT] = racc[r];

        // column-side partials: slot (a, h)
        if (!diag) {
            __syncthreads();
            if (t < CT) {
                float c = ((wacc[0][t] + wacc[1][t]) + (wacc[2][t] + wacc[3][t]));
                g_denom[(size_t)(a * CSPLIT + h) * TWO_N + jbase + t] = c;
            }
        }
    }
}

// ---------------------------------------------------------------------------
// Kernel 2: denom combine (8 threads/row x 16 slots) + positives + full reduce
// grid = 256, block = 256 (32 rows per block); last block finalizes
// ---------------------------------------------------------------------------
__global__ void __launch_bounds__(256)
fin_kernel(const float* __restrict__ zi, const float* __restrict__ zj,
           float* __restrict__ out) {
    __shared__ float sacc[8][32];
    const int t = threadIdx.x;
    const int r = t & 31;          // row within block
    const int g = t >> 5;          // slot group (16 slots each)
    const int i = blockIdx.x * 32 + r;

    float d = 0.0f;
    #pragma unroll
    for (int c = 0; c < 16; ++c)
        d += g_denom[(size_t)(g * 16 + c) * TWO_N + i];
    sacc[g][r] = d;
    __syncthreads();

    if (g == 0) {                  // warp 0 finishes the 32 rows
        float denom = 0.0f;
        #pragma unroll
        for (int ww = 0; ww < 8; ++ww) denom += sacc[ww][r];

        const u64 c10 = pack2(1.0f, 0.0f);

        float4 ua, ub;
        load_point(zi, zj, i, ua, ub);
        u64 Ai[5], Bi[5];
        build_a(ua, ub, Ai);
        build_b(ua, ub, Bi);
        denom -= chain_e(dotx(Ai, Bi, c10));      // bit-exact self cancel

        const int pp = (i < N_HALF) ? (i + N_HALF) : (i - N_HALF);
        float4 va, vb;
        load_point(zi, zj, pp, va, vb);
        u64 Bp[5];
        build_b(va, vb, Bp);
        float sim = chain_sim(dotx(Ai, Bp, c10));

        float loss = fast_lg2(denom) * LN2_F - 2.0f * sim;
        #pragma unroll
        for (int s = 16; s > 0; s >>= 1)
            loss += __shfl_xor_sync(0xFFFFFFFFu, loss, s);

        unsigned tk = 0u;
        if (r == 0) {
            g_partial[blockIdx.x] = loss;
            __threadfence();
            tk = atomicAdd(&g_cnt, 1u) + 1u;
        }
        tk = __shfl_sync(0xFFFFFFFFu, tk, 0);
        if (tk == 256u) {                          // last block finalizes
            __threadfence();
            float v = 0.0f;
            #pragma unroll
            for (int j = 0; j < 8; ++j) v += g_partial[r + j * 32];
            #pragma unroll
            for (int s = 16; s > 0; s >>= 1)
                v += __shfl_xor_sync(0xFFFFFFFFu, v, s);
            if (r == 0) {
                out[0] = v / (float)TWO_N;
                g_cnt = 0;                         // reset for next replay
            }
        }
    }
}

// ---------------------------------------------------------------------------
extern "C" void kernel_launch(void* const* d_in, const int* in_sizes, int n_in,
                              void* d_out, int out_size) {
    const float* zi = (const float*)d_in[0];
    const float* zj = (const float*)d_in[1];
    float* out = (float*)d_out;

    pair_kernel<<<GRID, BT>>>(zi, zj);
    fin_kernel<<<256, 256>>>(zi, zj, out);
}

// round 10
// speedup vs baseline: 1.0509x; 1.0060x over previous
#include <cuda_runtime.h>

#define N_HALF 4096
#define TWO_N  8192
#define D      8
#define NT     16                    // row/col tiles of 512
#define RT     512
#define BT     128                   // threads per block
#define ROWS_PT 4                    // rows per thread (RT = 4*BT)
#define CSPLIT 8                     // column octants per tile
#define CT     64                    // columns per block
#define NSLOT  (NT * CSPLIT)         // 128 partial slots per row
#define NPAIR  (NT * (NT + 1) / 2)   // 136 tile pairs
#define NITEM  (NPAIR * CSPLIT)      // 1088 work items
#define GRID   544                   // all-resident persistent grid (<= 4/SM x 148)
#define FINB   256                   // blocks that run the fin phase

#define LN2_F          0.6931471805599453f
#define HALF_LN2SQ_F   0.24022650695910072f   // ln2^2 / 2
#define HALF_LN2_F     0.34657359027997264f   // ln2 / 2
#define BOUNDARY_F     0.99999f

// __device__ scratch (allocation-free rule); zero-initialized at module load,
// and all counters are reset to 0 at the end of every run (graph-replay safe).
__device__ float        g_denom[NSLOT * TWO_N];   // 4 MB partials
__device__ float        g_partial[FINB];
__device__ unsigned int g_item;    // phase-1 work-steal counter
__device__ unsigned int g_cnt;     // phase-1 completion counter
__device__ unsigned int g_cnt2;    // phase-2 completion counter

typedef unsigned long long u64;

__device__ __forceinline__ float fast_sqrt(float x) { float y; asm("sqrt.approx.f32 %0, %1;" : "=f"(y) : "f"(x)); return y; }
__device__ __forceinline__ float fast_lg2(float x)  { float y; asm("lg2.approx.f32 %0, %1;"  : "=f"(y) : "f"(x)); return y; }
__device__ __forceinline__ float fast_ex2(float x)  { float y; asm("ex2.approx.f32 %0, %1;"  : "=f"(y) : "f"(x)); return y; }

// Reciprocal on the FMA/ALU pipes (keeps MUFU free): seed + 2 Newton steps.
__device__ __forceinline__ float rcp_alu(float d) {
    float y = __int_as_float(0x7EF311C3 - __float_as_int(d));
    y = __fmul_rn(y, fmaf(-d, y, 2.0f));
    y = __fmul_rn(y, fmaf(-d, y, 2.0f));
    return y;
}

__device__ __forceinline__ u64 pack2(float lo, float hi) {
    u64 r; asm("mov.b64 %0, {%1,%2};" : "=l"(r) : "f"(lo), "f"(hi)); return r;
}
__device__ __forceinline__ void unpack2(u64 v, float& lo, float& hi) {
    asm("mov.b64 {%0,%1}, %2;" : "=f"(lo), "=f"(hi) : "l"(v));
}
__device__ __forceinline__ u64 fma2(u64 a, u64 b, u64 c) {
    u64 r; asm("fma.rn.f32x2 %0, %1, %2, %3;" : "=l"(r) : "l"(a), "l"(b), "l"(c)); return r;
}

// ---- shared building blocks (single definition: bit-exact self-term cancel)
__device__ __forceinline__ void load_point(const float* __restrict__ zi,
                                           const float* __restrict__ zj,
                                           int i, float4& a, float4& b) {
    const float* src = (i < N_HALF) ? (zi + (size_t)i * D)
                                    : (zj + (size_t)(i - N_HALF) * D);
    a = *reinterpret_cast<const float4*>(src);
    b = *reinterpret_cast<const float4*>(src + 4);
}

__device__ __forceinline__ float raw8(const float4& a, const float4& b) {
    float d = __fmul_rn(a.x, a.x);
    d = fmaf(a.y, a.y, d); d = fmaf(a.z, a.z, d); d = fmaf(a.w, a.w, d);
    d = fmaf(b.x, b.x, d); d = fmaf(b.y, b.y, d); d = fmaf(b.z, b.z, d);
    d = fmaf(b.w, b.w, d);
    return d;
}

// row-side augmented vector: a = [-4*inv*z(8); 2*inv*raw; 2*inv]
__device__ __forceinline__ void build_a(const float4& a, const float4& b, u64 A[5]) {
    float raw = raw8(a, b);
    float inv = 1.0f / (1.0f - fminf(raw, BOUNDARY_F));
    float m   = __fmul_rn(-4.0f, inv);
    A[0] = pack2(__fmul_rn(m, a.x), __fmul_rn(m, a.y));
    A[1] = pack2(__fmul_rn(m, a.z), __fmul_rn(m, a.w));
    A[2] = pack2(__fmul_rn(m, b.x), __fmul_rn(m, b.y));
    A[3] = pack2(__fmul_rn(m, b.z), __fmul_rn(m, b.w));
    float i2 = __fadd_rn(inv, inv);
    A[4] = pack2(__fmul_rn(i2, raw), i2);
}

// col-side augmented vector: b = [inv*z(8); inv; inv*raw]
__device__ __forceinline__ void build_b(const float4& a, const float4& b, u64 B[5]) {
    float raw = raw8(a, b);
    float inv = 1.0f / (1.0f - fminf(raw, BOUNDARY_F));
    B[0] = pack2(__fmul_rn(inv, a.x), __fmul_rn(inv, a.y));
    B[1] = pack2(__fmul_rn(inv, a.z), __fmul_rn(inv, a.w));
    B[2] = pack2(__fmul_rn(inv, b.x), __fmul_rn(inv, b.y));
    B[3] = pack2(__fmul_rn(inv, b.z), __fmul_rn(inv, b.w));
    B[4] = pack2(inv, __fmul_rn(inv, raw));
}

// x = max(1 + a.b, 1)
__device__ __forceinline__ float dotx(const u64 A[5], const u64 B[5], u64 c10) {
    u64 s = fma2(A[4], B[4], c10);
    s = fma2(A[0], B[0], s);
    s = fma2(A[1], B[1], s);
    s = fma2(A[2], B[2], s);
    s = fma2(A[3], B[3], s);
    float lo, hi;
    unpack2(s, lo, hi);
    return fmaxf(__fadd_rn(lo, hi), 1.0f);
}

// e = exp(2*sim) = ex2( 1 / ((1 + arcosh(x)) * ln2/2) )   -- 3 MUFU + ALU rcp
__device__ __forceinline__ float chain_e(float x) {
    float x2 = fmaf(x, x, -1.0f);                  // >= 0 since x >= 1
    float s  = fast_sqrt(x2);                      // MUFU
    float l  = fast_lg2(__fadd_rn(x, s));          // MUFU
    float dn = fmaf(l, HALF_LN2SQ_F, HALF_LN2_F);  // (1+dist)*ln2/2
    return fast_ex2(rcp_alu(dn));                  // MUFU
}
// sim = 1/(1+arcosh(x))  (positives only; 2N evals)
__device__ __forceinline__ float chain_sim(float x) {
    float x2 = fmaf(x, x, -1.0f);
    float s  = fast_sqrt(x2);
    float l  = fast_lg2(__fadd_rn(x, s));
    return rcp_alu(fmaf(l, LN2_F, 1.0f));
}

// ---------------------------------------------------------------------------
// Fused persistent kernel: phase 1 = pairwise tiles (work-stealing over 1088
// items), software global barrier, phase 2 = denom combine + loss reduce.
// grid = 544 (all resident by construction), block = 128.
// ---------------------------------------------------------------------------
__global__ void __launch_bounds__(BT, 4)
fused_kernel(const float* __restrict__ zi, const float* __restrict__ zj,
             float* __restrict__ out) {
    __shared__ u64   sb[5][CT];     // column augmented vectors (SoA)
    __shared__ float wacc[4][CT];   // per-warp column sums / fin slot sums
    __shared__ unsigned int s_item;

    const int t    = threadIdx.x;
    const int lane = t & 31;
    const int w    = t >> 5;
    const int nxt  = (lane + 1) & 31;
    const u64 c10  = pack2(1.0f, 0.0f);

    // ---------------- Phase 1: pairwise work items --------------------------
    for (;;) {
        __syncthreads();                       // protect sb/wacc/s_item reuse
        if (t == 0) s_item = atomicAdd(&g_item, 1u);
        __syncthreads();
        const int item = (int)s_item;
        if (item >= NITEM) break;              // block-uniform

        // decode (a, b, h)
        int p = item >> 3;
        int h = item & 7;
        int a = 0, rem = p;
        while (rem >= NT - a) { rem -= NT - a; ++a; }
        int b = a + rem;
        const bool diag = (a == b);
        const int jbase = b * RT + h * CT;

        // stage 64 columns
        if (t < CT) {
            float4 ca, cb;
            load_point(zi, zj, jbase + t, ca, cb);
            u64 B[5];
            build_b(ca, cb, B);
            sb[0][t] = B[0]; sb[1][t] = B[1]; sb[2][t] = B[2];
            sb[3][t] = B[3]; sb[4][t] = B[4];
        }

        // build 4 row vectors
        u64 A[ROWS_PT][5];
        #pragma unroll
        for (int r = 0; r < ROWS_PT; ++r) {
            float4 ra, rb;
            load_point(zi, zj, a * RT + r * BT + t, ra, rb);
            build_a(ra, rb, A[r]);
        }

        __syncthreads();

        float racc[ROWS_PT] = {0.f, 0.f, 0.f, 0.f};

        if (diag) {
            #pragma unroll 4
            for (int c = 0; c < CT; ++c) {                    // broadcast LDS
                u64 B[5] = { sb[0][c], sb[1][c], sb[2][c], sb[3][c], sb[4][c] };
                #pragma unroll
                for (int r = 0; r < ROWS_PT; ++r)
                    racc[r] += chain_e(dotx(A[r], B, c10));
            }
        } else {
            #pragma unroll
            for (int g = 0; g < CT / 32; ++g) {
                float cacc = 0.0f;                            // systolic ring acc
                #pragma unroll 4
                for (int k = 0; k < 32; ++k) {
                    int c = (g << 5) + ((lane + k) & 31);     // conflict-free
                    u64 B[5] = { sb[0][c], sb[1][c], sb[2][c], sb[3][c], sb[4][c] };
                    float e0 = chain_e(dotx(A[0], B, c10));
                    float e1 = chain_e(dotx(A[1], B, c10));
                    float e2 = chain_e(dotx(A[2], B, c10));
                    float e3 = chain_e(dotx(A[3], B, c10));
                    racc[0] += e0; racc[1] += e1; racc[2] += e2; racc[3] += e3;
                    cacc += ((e0 + e1) + (e2 + e3));
                    cacc = __shfl_sync(0xFFFFFFFFu, cacc, nxt, 32);
                }
                wacc[w][(g << 5) + lane] = cacc;              // lane holds col
            }
        }

        // row-side partials: slot (b, h)
        const size_t rbase = (size_t)(b * CSPLIT + h) * TWO_N + a * RT + t;
        #pragma unroll
        for (int r = 0; r < ROWS_PT; ++r)
            g_denom[rbase + (size_t)r * BT] = racc[r];

        // column-side partials: slot (a, h)
        if (!diag) {
            __syncthreads();
            if (t < CT) {
                float c = ((wacc[0][t] + wacc[1][t]) + (wacc[2][t] + wacc[3][t]));
                g_denom[(size_t)(a * CSPLIT + h) * TWO_N + jbase + t] = c;
            }
        }
    }

    // ---------------- Global barrier (release -> spin acquire) --------------
    __syncthreads();
    __threadfence();
    if (t == 0) atomicAdd(&g_cnt, 1u);

    if (blockIdx.x >= FINB) return;            // non-fin blocks exit

    if (t == 0) {
        while (*((volatile unsigned int*)&g_cnt) < GRID) { __nanosleep(64); }
    }
    __syncthreads();
    __threadfence();                           // acquire: order g_denom reads

    // ---------------- Phase 2: denom combine + loss -------------------------
    {
        const int r = t & 31;                  // row within block
        const int g = t >> 5;                  // slot group (32 slots each)
        const int i = blockIdx.x * 32 + r;

        float d = 0.0f;
        #pragma unroll
        for (int c = 0; c < 32; ++c)
            d += g_denom[(size_t)(g * 32 + c) * TWO_N + i];
        wacc[g][r] = d;
        __syncthreads();

        if (g == 0) {                          // warp 0 finishes the 32 rows
            float denom = ((wacc[0][r] + wacc[1][r]) + (wacc[2][r] + wacc[3][r]));

            float4 ua, ub;
            load_point(zi, zj, i, ua, ub);
            u64 Ai[5], Bi[5];
            build_a(ua, ub, Ai);
            build_b(ua, ub, Bi);
            denom -= chain_e(dotx(Ai, Bi, c10));   // bit-exact self cancel

            const int pp = (i < N_HALF) ? (i + N_HALF) : (i - N_HALF);
            float4 va, vb;
            load_point(zi, zj, pp, va, vb);
            u64 Bp[5];
            build_b(va, vb, Bp);
            float sim = chain_sim(dotx(Ai, Bp, c10));

            float loss = fast_lg2(denom) * LN2_F - 2.0f * sim;
            #pragma unroll
            for (int s = 16; s > 0; s >>= 1)
                loss += __shfl_xor_sync(0xFFFFFFFFu, loss, s);

            unsigned tk = 0u;
            if (r == 0) {
                g_partial[blockIdx.x] = loss;
                __threadfence();
                tk = atomicAdd(&g_cnt2, 1u) + 1u;
            }
            tk = __shfl_sync(0xFFFFFFFFu, tk, 0);
            if (tk == FINB) {                      // last fin block finalizes
                __threadfence();
                float v = 0.0f;
                #pragma unroll
                for (int j = 0; j < 8; ++j) v += g_partial[r + j * 32];
                #pragma unroll
                for (int s = 16; s > 0; s >>= 1)
                    v += __shfl_xor_sync(0xFFFFFFFFu, v, s);
                if (r == 0) {
                    out[0] = v / (float)TWO_N;
                    // reset counters for the next graph replay (all readers done)
                    g_item = 0u;
                    g_cnt  = 0u;
                    g_cnt2 = 0u;
                    __threadfence();
                }
            }
        }
    }
}

// ---------------------------------------------------------------------------
extern "C" void kernel_launch(void* const* d_in, const int* in_sizes, int n_in,
                              void* d_out, int out_size) {
    const float* zi = (const float*)d_in[0];
    const float* zj = (const float*)d_in[1];
    float* out = (float*)d_out;

    fused_kernel<<<GRID, BT>>>(zi, zj, out);
}

// round 11
// speedup vs baseline: 1.0860x; 1.0334x over previous
#include <cuda_runtime.h>

#define N_HALF 4096
#define TWO_N  8192
#define D      8
#define NT     16                    // row/col tiles of 512
#define RT     512
#define BT     128                   // threads per block
#define ROWS_PT 4                    // rows per thread (RT = 4*BT)
#define CSPLIT 16                    // column 32-col slices per tile
#define CT     32                    // columns per work item
#define NSLOT  (NT * CSPLIT)         // 256 partial slots per row
#define NPAIR  (NT * (NT + 1) / 2)   // 136 tile pairs
#define NITEM  (NPAIR * CSPLIT)      // 2176 work items
#define GRID   740                   // 5 blocks/SM x 148 SMs
#define FINB   256                   // blocks that run the fin phase

#define LN2_F          0.6931471805599453f
#define HALF_LN2SQ_F   0.24022650695910072f   // ln2^2 / 2
#define HALF_LN2_F     0.34657359027997264f   // ln2 / 2
#define BOUNDARY_F     0.99999f

// __device__ scratch (allocation-free rule); zero-initialized at module load,
// all counters reset at end of every run (graph-replay safe).
__device__ float        g_denom[NSLOT * TWO_N];   // 8 MB partials
__device__ float        g_partial[FINB];
__device__ unsigned int g_item;    // phase-1 work-steal counter
__device__ unsigned int g_cnt;     // phase-1 completion counter
__device__ unsigned int g_cnt2;    // phase-2 completion counter

typedef unsigned long long u64;

__device__ __forceinline__ float fast_sqrt(float x) { float y; asm("sqrt.approx.f32 %0, %1;" : "=f"(y) : "f"(x)); return y; }
__device__ __forceinline__ float fast_lg2(float x)  { float y; asm("lg2.approx.f32 %0, %1;"  : "=f"(y) : "f"(x)); return y; }
__device__ __forceinline__ float fast_ex2(float x)  { float y; asm("ex2.approx.f32 %0, %1;"  : "=f"(y) : "f"(x)); return y; }

// Reciprocal on the FMA/ALU pipes (keeps MUFU free): seed + 2 Newton steps.
__device__ __forceinline__ float rcp_alu(float d) {
    float y = __int_as_float(0x7EF311C3 - __float_as_int(d));
    y = __fmul_rn(y, fmaf(-d, y, 2.0f));
    y = __fmul_rn(y, fmaf(-d, y, 2.0f));
    return y;
}

__device__ __forceinline__ u64 pack2(float lo, float hi) {
    u64 r; asm("mov.b64 %0, {%1,%2};" : "=l"(r) : "f"(lo), "f"(hi)); return r;
}
__device__ __forceinline__ void unpack2(u64 v, float& lo, float& hi) {
    asm("mov.b64 {%0,%1}, %2;" : "=f"(lo), "=f"(hi) : "l"(v));
}
__device__ __forceinline__ u64 fma2(u64 a, u64 b, u64 c) {
    u64 r; asm("fma.rn.f32x2 %0, %1, %2, %3;" : "=l"(r) : "l"(a), "l"(b), "l"(c)); return r;
}

// ---- shared building blocks (single definition: bit-exact self-term cancel)
__device__ __forceinline__ void load_point(const float* __restrict__ zi,
                                           const float* __restrict__ zj,
                                           int i, float4& a, float4& b) {
    const float* src = (i < N_HALF) ? (zi + (size_t)i * D)
                                    : (zj + (size_t)(i - N_HALF) * D);
    a = *reinterpret_cast<const float4*>(src);
    b = *reinterpret_cast<const float4*>(src + 4);
}

__device__ __forceinline__ float raw8(const float4& a, const float4& b) {
    float d = __fmul_rn(a.x, a.x);
    d = fmaf(a.y, a.y, d); d = fmaf(a.z, a.z, d); d = fmaf(a.w, a.w, d);
    d = fmaf(b.x, b.x, d); d = fmaf(b.y, b.y, d); d = fmaf(b.z, b.z, d);
    d = fmaf(b.w, b.w, d);
    return d;
}

// row-side augmented vector: a = [-4*inv*z(8); 2*inv*raw; 2*inv]
__device__ __forceinline__ void build_a(const float4& a, const float4& b, u64 A[5]) {
    float raw = raw8(a, b);
    float inv = 1.0f / (1.0f - fminf(raw, BOUNDARY_F));
    float m   = __fmul_rn(-4.0f, inv);
    A[0] = pack2(__fmul_rn(m, a.x), __fmul_rn(m, a.y));
    A[1] = pack2(__fmul_rn(m, a.z), __fmul_rn(m, a.w));
    A[2] = pack2(__fmul_rn(m, b.x), __fmul_rn(m, b.y));
    A[3] = pack2(__fmul_rn(m, b.z), __fmul_rn(m, b.w));
    float i2 = __fadd_rn(inv, inv);
    A[4] = pack2(__fmul_rn(i2, raw), i2);
}

// col-side augmented vector: b = [inv*z(8); inv; inv*raw]
__device__ __forceinline__ void build_b(const float4& a, const float4& b, u64 B[5]) {
    float raw = raw8(a, b);
    float inv = 1.0f / (1.0f - fminf(raw, BOUNDARY_F));
    B[0] = pack2(__fmul_rn(inv, a.x), __fmul_rn(inv, a.y));
    B[1] = pack2(__fmul_rn(inv, a.z), __fmul_rn(inv, a.w));
    B[2] = pack2(__fmul_rn(inv, b.x), __fmul_rn(inv, b.y));
    B[3] = pack2(__fmul_rn(inv, b.z), __fmul_rn(inv, b.w));
    B[4] = pack2(inv, __fmul_rn(inv, raw));
}

// x = max(1 + a.b, 1)
__device__ __forceinline__ float dotx(const u64 A[5], const u64 B[5], u64 c10) {
    u64 s = fma2(A[4], B[4], c10);
    s = fma2(A[0], B[0], s);
    s = fma2(A[1], B[1], s);
    s = fma2(A[2], B[2], s);
    s = fma2(A[3], B[3], s);
    float lo, hi;
    unpack2(s, lo, hi);
    return fmaxf(__fadd_rn(lo, hi), 1.0f);
}

// e = exp(2*sim) = ex2( 1 / ((1 + arcosh(x)) * ln2/2) )   -- 3 MUFU + ALU rcp
__device__ __forceinline__ float chain_e(float x) {
    float x2 = fmaf(x, x, -1.0f);                  // >= 0 since x >= 1
    float s  = fast_sqrt(x2);                      // MUFU
    float l  = fast_lg2(__fadd_rn(x, s));          // MUFU
    float dn = fmaf(l, HALF_LN2SQ_F, HALF_LN2_F);  // (1+dist)*ln2/2
    return fast_ex2(rcp_alu(dn));                  // MUFU
}
// sim = 1/(1+arcosh(x))  (positives only; 2N evals)
__device__ __forceinline__ float chain_sim(float x) {
    float x2 = fmaf(x, x, -1.0f);
    float s  = fast_sqrt(x2);
    float l  = fast_lg2(__fadd_rn(x, s));
    return rcp_alu(fmaf(l, LN2_F, 1.0f));
}

// ---------------------------------------------------------------------------
// Fused persistent kernel: phase 1 = pairwise tiles (work-stealing over 2176
// items), software global barrier, phase 2 = denom combine + loss reduce.
// grid = 740 (5 blocks/SM), block = 128.
// ---------------------------------------------------------------------------
__global__ void __launch_bounds__(BT, 5)
fused_kernel(const float* __restrict__ zi, const float* __restrict__ zj,
             float* __restrict__ out) {
    __shared__ u64   sb[5][CT];     // column augmented vectors (SoA)
    __shared__ float wacc[4][CT];   // per-warp column sums / fin slot sums
    __shared__ unsigned int s_item;

    const int t    = threadIdx.x;
    const int lane = t & 31;
    const int w    = t >> 5;
    const int nxt  = (lane + 1) & 31;
    const u64 c10  = pack2(1.0f, 0.0f);

    // ---------------- Phase 1: pairwise work items --------------------------
    for (;;) {
        __syncthreads();                       // protect sb/wacc/s_item reuse
        if (t == 0) s_item = atomicAdd(&g_item, 1u);
        __syncthreads();
        const int item = (int)s_item;
        if (item >= NITEM) break;              // block-uniform

        // decode (a, b, h)
        int p = item >> 4;
        int h = item & 15;
        int a = 0, rem = p;
        while (rem >= NT - a) { rem -= NT - a; ++a; }
        int b = a + rem;
        const bool diag = (a == b);
        const int jbase = b * RT + h * CT;

        // stage 32 columns
        if (t < CT) {
            float4 ca, cb;
            load_point(zi, zj, jbase + t, ca, cb);
            u64 B[5];
            build_b(ca, cb, B);
            sb[0][t] = B[0]; sb[1][t] = B[1]; sb[2][t] = B[2];
            sb[3][t] = B[3]; sb[4][t] = B[4];
        }

        // build 4 row vectors
        u64 A[ROWS_PT][5];
        #pragma unroll
        for (int r = 0; r < ROWS_PT; ++r) {
            float4 ra, rb;
            load_point(zi, zj, a * RT + r * BT + t, ra, rb);
            build_a(ra, rb, A[r]);
        }

        __syncthreads();

        float racc[ROWS_PT] = {0.f, 0.f, 0.f, 0.f};

        if (diag) {
            #pragma unroll 4
            for (int c = 0; c < CT; ++c) {                    // broadcast LDS
                u64 B[5] = { sb[0][c], sb[1][c], sb[2][c], sb[3][c], sb[4][c] };
                #pragma unroll
                for (int r = 0; r < ROWS_PT; ++r)
                    racc[r] += chain_e(dotx(A[r], B, c10));
            }
        } else {
            float cacc = 0.0f;                                // systolic ring acc
            #pragma unroll 4
            for (int k = 0; k < 32; ++k) {
                int c = (lane + k) & 31;                      // conflict-free
                u64 B[5] = { sb[0][c], sb[1][c], sb[2][c], sb[3][c], sb[4][c] };
                float e0 = chain_e(dotx(A[0], B, c10));
                float e1 = chain_e(dotx(A[1], B, c10));
                float e2 = chain_e(dotx(A[2], B, c10));
                float e3 = chain_e(dotx(A[3], B, c10));
                racc[0] += e0; racc[1] += e1; racc[2] += e2; racc[3] += e3;
                cacc += ((e0 + e1) + (e2 + e3));
                cacc = __shfl_sync(0xFFFFFFFFu, cacc, nxt, 32);
            }
            wacc[w][lane] = cacc;                             // lane holds col
        }

        // row-side partials: slot (b, h)
        const size_t rbase = (size_t)(b * CSPLIT + h) * TWO_N + a * RT + t;
        #pragma unroll
        for (int r = 0; r < ROWS_PT; ++r)
            g_denom[rbase + (size_t)r * BT] = racc[r];

        // column-side partials: slot (a, h)
        if (!diag) {
            __syncthreads();
            if (t < CT) {
                float c = ((wacc[0][t] + wacc[1][t]) + (wacc[2][t] + wacc[3][t]));
                g_denom[(size_t)(a * CSPLIT + h) * TWO_N + jbase + t] = c;
            }
        }
    }

    // ---------------- Global barrier (release -> spin acquire) --------------
    __syncthreads();
    __threadfence();
    if (t == 0) atomicAdd(&g_cnt, 1u);

    if (blockIdx.x >= FINB) return;            // non-fin blocks exit, free slots

    if (t == 0) {
        while (*((volatile unsigned int*)&g_cnt) < GRID) { __nanosleep(64); }
    }
    __syncthreads();
    __threadfence();                           // acquire: order g_denom reads

    // ---------------- Phase 2: denom combine + loss -------------------------
    {
        const int r = t & 31;                  // row within block
        const int g = t >> 5;                  // slot group (64 slots each)
        const int i = blockIdx.x * 32 + r;

        float d = 0.0f;
        #pragma unroll
        for (int c = 0; c < 64; ++c)
            d += g_denom[(size_t)(g * 64 + c) * TWO_N + i];
        wacc[g][r] = d;
        __syncthreads();

        if (g == 0) {                          // warp 0 finishes the 32 rows
            float denom = ((wacc[0][r] + wacc[1][r]) + (wacc[2][r] + wacc[3][r]));

            float4 ua, ub;
            load_point(zi, zj, i, ua, ub);
            u64 Ai[5], Bi[5];
            build_a(ua, ub, Ai);
            build_b(ua, ub, Bi);
            denom -= chain_e(dotx(Ai, Bi, c10));   // bit-exact self cancel

            const int pp = (i < N_HALF) ? (i + N_HALF) : (i - N_HALF);
            float4 va, vb;
            load_point(zi, zj, pp, va, vb);
            u64 Bp[5];
            build_b(va, vb, Bp);
            float sim = chain_sim(dotx(Ai, Bp, c10));

            float loss = fast_lg2(denom) * LN2_F - 2.0f * sim;
            #pragma unroll
            for (int s = 16; s > 0; s >>= 1)
                loss += __shfl_xor_sync(0xFFFFFFFFu, loss, s);

            unsigned tk = 0u;
            if (r == 0) {
                g_partial[blockIdx.x] = loss;
                __threadfence();
                tk = atomicAdd(&g_cnt2, 1u) + 1u;
            }
            tk = __shfl_sync(0xFFFFFFFFu, tk, 0);
            if (tk == FINB) {                      // last fin block finalizes
                __threadfence();
                float v = 0.0f;
                #pragma unroll
                for (int j = 0; j < 8; ++j) v += g_partial[r + j * 32];
                #pragma unroll
                for (int s = 16; s > 0; s >>= 1)
                    v += __shfl_xor_sync(0xFFFFFFFFu, v, s);
                if (r == 0) {
                    out[0] = v / (float)TWO_N;
                    // reset counters for next graph replay (all readers done)
                    g_item = 0u;
                    g_cnt  = 0u;
                    g_cnt2 = 0u;
                    __threadfence();
                }
            }
        }
    }
}

// ---------------------------------------------------------------------------
extern "C" void kernel_launch(void* const* d_in, const int* in_sizes, int n_in,
                              void* d_out, int out_size) {
    const float* zi = (const float*)d_in[0];
    const float* zj = (const float*)d_in[1];
    float* out = (float*)d_out;

    fused_kernel<<<GRID, BT>>>(zi, zj, out);
}